// round 13
// baseline (speedup 1.0000x reference)
#include <cuda_runtime.h>
#include <cuda_bf16.h>
#include <cstdint>
#include <math.h>

// ---------------- problem constants ----------------
#define BB     64
#define D0     4096
#define D1     1024
#define D2OUT  1000
#define TT     32
#define MROWS  (BB * TT)          // 2048 GEMM rows
#define DELTA  1e-3f              // borderline-gap threshold for exact fix-up

// ---------------- device scratch (static globals; no runtime alloc) ----------------
__device__ __nv_bfloat16 g_Bh[(size_t)D0 * D0];    // w0 hi split
__device__ __nv_bfloat16 g_Bm[(size_t)D0 * D0];    // w0 mid split
__device__ __nv_bfloat16 g_B2h[(size_t)D1 * D1];   // w2 splits; rows >= 1000 stay zero
__device__ __nv_bfloat16 g_B2m[(size_t)D1 * D1];
__device__ __nv_bfloat16 g_A[(size_t)MROWS * D0];  // spike matrix (ld 4096 L0 / 1024 L2)
__device__ int           g_cnt0[BB * D0];
__device__ unsigned char g_N1[BB * D1];
__device__ int           g_cnt2[BB * D2OUT];
__device__ unsigned char g_flag0[BB * D0];
__device__ unsigned char g_flag2[BB * D2OUT];
__device__ uint32_t      g_ord0[BB * D0];
__device__ int           g_seg0[BB * 34];
__device__ uint32_t      g_ord2[BB * D1];
__device__ int           g_seg2[BB * 34];
__device__ int           g_nwork0;                 // worklist sizes (zeroed each launch)
__device__ int           g_nwork2;
__device__ uint32_t      g_work0[BB * D0];         // packed flagged indices b*JMAX+j
__device__ uint32_t      g_work2[BB * D2OUT];

// ---------------- PTX helpers (base sm_103-legal only) ----------------
__device__ __forceinline__ uint32_t smem_u32(const void* p) {
    uint32_t a;
    asm("{ .reg .u64 t; cvta.to.shared.u64 t, %1; cvt.u32.u64 %0, t; }" : "=r"(a) : "l"(p));
    return a;
}
#define CP_ASYNC16(dst, src) \
    asm volatile("cp.async.cg.shared.global [%0], [%1], 16;" :: "r"(dst), "l"(src) : "memory")
#define CP_COMMIT() asm volatile("cp.async.commit_group;" ::: "memory")
#define CP_WAIT1()  asm volatile("cp.async.wait_group 1;" ::: "memory")
#define CP_WAIT0()  asm volatile("cp.async.wait_group 0;" ::: "memory")
#define LDSM4(r0, r1, r2, r3, addr)                                              \
    asm volatile("ldmatrix.sync.aligned.m8n8.x4.shared.b16 {%0,%1,%2,%3}, [%4];" \
                 : "=r"(r0), "=r"(r1), "=r"(r2), "=r"(r3) : "r"(addr))
#define MMA16816(d, a, b0, b1)                                                      \
    asm volatile("mma.sync.aligned.m16n8k16.row.col.f32.bf16.bf16.f32 "             \
                 "{%0,%1,%2,%3},{%4,%5,%6,%7},{%8,%9},{%0,%1,%2,%3};"               \
                 : "+f"((d)[0]), "+f"((d)[1]), "+f"((d)[2]), "+f"((d)[3])           \
                 : "r"((a)[0]), "r"((a)[1]), "r"((a)[2]), "r"((a)[3]),              \
                   "r"(b0), "r"(b1))
#define SWZ128(off) ((off) ^ (((off) >> 3) & 0x70))

// ---------------- uniform spike pattern (reference fp32 semantics) ----------------
__device__ __forceinline__ uint32_t pattern_mask(int n) {
    if (n <= 0)  return 0u;
    if (n >= TT) return 0xFFFFFFFFu;
    float spacing = __fdiv_rn(32.0f, (float)n);
    uint32_t m = 0u;
    for (int c = 0; c < TT; c++) {
        double r = fmod((double)c, (double)spacing);
        if (r < 1.0) m |= (1u << c);
    }
    return m;
}

// ---------------- weight splits: w = hi + mid (+ tiny residual handled by fix-up) ------
__global__ void split0_kernel(const float* __restrict__ w) {
    size_t idx = (size_t)blockIdx.x * 256 + threadIdx.x;
    float wv = w[idx];
    __nv_bfloat16 h = __float2bfloat16(wv);
    g_Bh[idx] = h; g_Bm[idx] = __float2bfloat16(wv - __bfloat162float(h));
}
__global__ void split2_kernel(const float* __restrict__ w) {
    size_t idx = (size_t)blockIdx.x * 256 + threadIdx.x;   // covers 1000*1024 exactly
    float wv = w[idx];
    __nv_bfloat16 h = __float2bfloat16(wv);
    g_B2h[idx] = h; g_B2m[idx] = __float2bfloat16(wv - __bfloat162float(h));
}

// ---------------- zero the worklist counters (fresh every launch) ----------------
__global__ void zero_kernel() { g_nwork0 = 0; g_nwork2 = 0; }

// ---------------- spike-matrix builds (bf16 {0,1}) ----------------
__global__ void buildA0_kernel(const float* __restrict__ x, const int* __restrict__ idx0) {
    __shared__ uint32_t spat[33];
    int tid = threadIdx.x;
    if (tid < 33) spat[tid] = pattern_mask(tid);
    __syncthreads();
    int b = blockIdx.y;
    int i = blockIdx.x * 256 + tid;
    float r = x[b * D0 + idx0[i]];
    uint32_t m = spat[__float2int_rn(r * 32.0f)];
    unsigned short* A = (unsigned short*)g_A;
#pragma unroll
    for (int t = 0; t < TT; t++)
        A[(size_t)(b * TT + t) * D0 + i] = ((m >> t) & 1u) ? (unsigned short)0x3F80 : (unsigned short)0;
}
__global__ void buildA2_kernel(const int* __restrict__ idx2) {
    __shared__ uint32_t spat[33];
    int tid = threadIdx.x;
    if (tid < 33) spat[tid] = pattern_mask(tid);
    __syncthreads();
    int b = blockIdx.y;
    int i = blockIdx.x * 256 + tid;
    uint32_t m = spat[g_N1[b * D1 + idx2[i]]];
    unsigned short* A = (unsigned short*)g_A;
#pragma unroll
    for (int t = 0; t < TT; t++)
        A[(size_t)(b * TT + t) * D1 + i] = ((m >> t) & 1u) ? (unsigned short)0x3F80 : (unsigned short)0;
}

// ---------------- deterministic bucket sort (spill-free; identical ord/seg to R1) ----------
template <int K>
__global__ void sort_kernel(const float* __restrict__ x, const int* __restrict__ idxg) {
    __shared__ unsigned char ns[K];
    __shared__ int cnt[128 * 33];
    __shared__ int base[34];
    int b = blockIdx.x, t = threadIdx.x;
    constexpr int CH = K / 128;

    if (K == D0) {
        for (int i = t; i < K; i += 128)
            ns[i] = (unsigned char)__float2int_rn(x[b * D0 + idxg[i]] * 32.0f);
    } else {
        for (int i = t; i < K; i += 128)
            ns[i] = g_N1[b * D1 + idxg[i]];
    }
#pragma unroll
    for (int n = 0; n < 33; n++) cnt[t * 33 + n] = 0;
    __syncthreads();
    for (int c = 0; c < CH; c++) cnt[t * 33 + ns[t * CH + c]]++;
    __syncthreads();
    if (t < 33) {
        int run = 0;
        for (int u = 0; u < 128; u++) { int v = cnt[u * 33 + t]; cnt[u * 33 + t] = run; run += v; }
        base[t] = run;
    }
    __syncthreads();
    if (t == 0) {
        int acc = 0;
        for (int n = 0; n < 33; n++) { int v = base[n]; base[n] = acc; acc += v; }
        base[33] = acc;
    }
    __syncthreads();
    uint32_t* ord = ((K == D0) ? g_ord0 : g_ord2) + (size_t)b * K;
    int* seg = ((K == D0) ? g_seg0 : g_seg2) + b * 34;
    for (int c = 0; c < CH; c++) {
        int i = t * CH + c;
        int n = ns[i];
        int pos = base[n] + cnt[t * 33 + n];
        cnt[t * 33 + n]++;
        ord[pos] = (uint32_t)i;
    }
    if (t < 34) seg[t] = base[t];
}

// ---------------- GEMM (2 bf16 splits) + fused LIF scan + borderline flagging ----------
// Exact R9 configuration: block 128x128, warp 32x64, K-chunk 64, 2-stage, 2 CTAs/SM.
template <int L>
__global__ void __launch_bounds__(256, 2) gemm_lif_kernel(const float* __restrict__ thr_p) {
    constexpr int KTOT = (L == 0) ? D0 : D1;
    constexpr int NC   = KTOT / 64;
    constexpr int JMAX = (L == 0) ? D0 : D2OUT;
    constexpr uint32_t STAGE = 49152u;   // A(16K) + Bh(16K) + Bm(16K)

    extern __shared__ char smem[];
    uint32_t sb = smem_u32(smem);
    int tid = threadIdx.x, wid = tid >> 5, lane = tid & 31;
    int n0 = blockIdx.x * 128, m0 = blockIdx.y * 128;
    int wm = wid >> 1, wn = wid & 1;
    const int mW = wm * 32, nW = wn * 64;

    const __nv_bfloat16* Bs[2];
    if (L == 0) { Bs[0] = g_Bh; Bs[1] = g_Bm; }
    else        { Bs[0] = g_B2h; Bs[1] = g_B2m; }

    auto load_stage = [&](int stage, int kc) {
        uint32_t st = sb + (uint32_t)stage * STAGE;
        int k0 = kc * 64;
#pragma unroll
        for (int u = 0; u < 4; u++) {
            int slot = u * 256 + tid, r = slot >> 3, kk = slot & 7;
            const __nv_bfloat16* gp = g_A + (size_t)(m0 + r) * KTOT + k0 + kk * 8;
            CP_ASYNC16(st + SWZ128((uint32_t)(r * 128 + kk * 16)), gp);
        }
#pragma unroll
        for (int s = 0; s < 2; s++) {
            uint32_t bb = st + 16384u * (1 + s);
#pragma unroll
            for (int u = 0; u < 4; u++) {
                int slot = u * 256 + tid, r = slot >> 3, kk = slot & 7;
                const __nv_bfloat16* gp = Bs[s] + (size_t)(n0 + r) * KTOT + k0 + kk * 8;
                CP_ASYNC16(bb + SWZ128((uint32_t)(r * 128 + kk * 16)), gp);
            }
        }
        CP_COMMIT();
    };

    float acc[2][8][4];
#pragma unroll
    for (int a = 0; a < 2; a++)
#pragma unroll
        for (int b = 0; b < 8; b++)
#pragma unroll
            for (int c = 0; c < 4; c++) acc[a][b][c] = 0.f;

    int q = lane >> 3, w8 = lane & 7;

    load_stage(0, 0);
#pragma unroll 1
    for (int c = 0; c < NC; c++) {
        if (c + 1 < NC) { load_stage((c + 1) & 1, c + 1); CP_WAIT1(); }
        else            { CP_WAIT0(); }
        __syncthreads();

        uint32_t st = sb + (uint32_t)(c & 1) * STAGE;
#pragma unroll
        for (int ks = 0; ks < 4; ks++) {
            uint32_t af[2][4];
#pragma unroll
            for (int mf = 0; mf < 2; mf++) {
                int row = mW + mf * 16 + w8 + (q & 1) * 8;
                int colb = ks * 32 + (q >> 1) * 16;
                LDSM4(af[mf][0], af[mf][1], af[mf][2], af[mf][3],
                      st + SWZ128((uint32_t)(row * 128 + colb)));
            }
#pragma unroll
            for (int s = 0; s < 2; s++) {
                uint32_t bbase = st + 16384u * (1 + s);
#pragma unroll
                for (int nfp = 0; nfp < 4; nfp++) {
                    uint32_t b0, b1, b2, b3;
                    int row = nW + nfp * 16 + w8 + (q >> 1) * 8;
                    int colb = ks * 32 + (q & 1) * 16;
                    LDSM4(b0, b1, b2, b3, bbase + SWZ128((uint32_t)(row * 128 + colb)));
                    MMA16816(acc[0][2 * nfp + 0], af[0], b0, b1);
                    MMA16816(acc[0][2 * nfp + 1], af[0], b2, b3);
                    MMA16816(acc[1][2 * nfp + 0], af[1], b0, b1);
                    MMA16816(acc[1][2 * nfp + 1], af[1], b2, b3);
                }
            }
        }
        __syncthreads();
    }

    // ---- epilogue: transpose C through padded smem tile, LIF scan + gap flag ----
    float* ct = (float*)smem;                         // [128][129] fp32 (66 KB < 96 KB)
#pragma unroll
    for (int mf = 0; mf < 2; mf++)
#pragma unroll
        for (int nf = 0; nf < 8; nf++) {
            int row = mW + mf * 16 + (lane >> 2);
            int col = nW + nf * 8 + 2 * (lane & 3);
            ct[row * 129 + col]           = acc[mf][nf][0];
            ct[row * 129 + col + 1]       = acc[mf][nf][1];
            ct[(row + 8) * 129 + col]     = acc[mf][nf][2];
            ct[(row + 8) * 129 + col + 1] = acc[mf][nf][3];
        }
    __syncthreads();

    float thr = *thr_p;
    int* cnt_out = (L == 0) ? g_cnt0 : g_cnt2;
    unsigned char* flag_out = (L == 0) ? g_flag0 : g_flag2;
#pragma unroll
    for (int pp = 0; pp < 2; pp++) {
        int p = pp * 256 + tid;
        int bl = p >> 7, j = p & 127;
        float memb = 0.f, ming = 1e30f;
        int cnt = 0;
#pragma unroll
        for (int t = 0; t < TT; t++) {
            memb += ct[(bl * 32 + t) * 129 + j];
            float g = fabsf(memb - thr);
            if (g < ming) ming = g;
            if (memb > thr) { memb -= thr; cnt++; }
        }
        int bglob = blockIdx.y * 4 + bl;
        int jglob = n0 + j;
        if (jglob < JMAX) {
            cnt_out[(size_t)bglob * JMAX + jglob] = cnt;
            flag_out[(size_t)bglob * JMAX + jglob] = (ming < DELTA) ? 1 : 0;
        }
    }
}

// ---------------- worklist compaction (order-independent results; atomics OK) ----------
template <int L>
__global__ void compact_kernel() {
    constexpr int JMAX = (L == 0) ? D0 : D2OUT;
    int idx = blockIdx.x * 256 + threadIdx.x;
    if (idx >= BB * JMAX) return;
    if (((L == 0) ? g_flag0 : g_flag2)[idx]) {
        int p = atomicAdd((L == 0) ? &g_nwork0 : &g_nwork2, 1);
        ((L == 0) ? g_work0 : g_work2)[p] = (uint32_t)idx;
    }
}

// ---------------- exact fix-up over the DENSE worklist (R9's bit-exact value order) ------
template <int L>
__global__ void fixup_kernel(const float* __restrict__ w, const float* __restrict__ thr_p) {
    constexpr int K    = (L == 0) ? D0 : D1;
    constexpr int JMAX = (L == 0) ? D0 : D2OUT;
    __shared__ uint32_t spat[33];
    int tid = threadIdx.x;
    if (tid < 33) spat[tid] = pattern_mask(tid);
    __syncthreads();

    int wi = blockIdx.x * 256 + tid;
    if (wi >= ((L == 0) ? g_nwork0 : g_nwork2)) return;
    int idx = (int)((L == 0) ? g_work0 : g_work2)[wi];
    int b = idx / JMAX, j = idx % JMAX;

    const uint32_t* po = ((L == 0) ? g_ord0 : g_ord2) + b * K;
    const int*      sg = ((L == 0) ? g_seg0 : g_seg2) + b * 34;
    const float* wrow = w + (size_t)j * K;

    float I[TT];
#pragma unroll
    for (int t = 0; t < TT; t++) I[t] = 0.f;

#pragma unroll 1
    for (int n = 1; n < 33; n++) {
        int s = sg[n], e = sg[n + 1];
        if (s >= e) continue;
        float a0 = 0.f, a1 = 0.f, a2 = 0.f, a3 = 0.f;
        int k = s;
        float p0 = 0.f, p1 = 0.f, p2 = 0.f, p3 = 0.f;
        if (k + 4 <= e) {
            p0 = wrow[po[k]]; p1 = wrow[po[k + 1]];
            p2 = wrow[po[k + 2]]; p3 = wrow[po[k + 3]];
        }
#pragma unroll 1
        for (; k + 4 <= e; ) {
            float c0 = p0, c1 = p1, c2 = p2, c3 = p3;
            int kn = k + 4;
            if (kn + 4 <= e) {
                p0 = wrow[po[kn]]; p1 = wrow[po[kn + 1]];
                p2 = wrow[po[kn + 2]]; p3 = wrow[po[kn + 3]];
            }
            a0 += c0; a1 += c1; a2 += c2; a3 += c3;   // R1 add order
            k = kn;
        }
        for (; k < e; k++) a0 += wrow[po[k]];
        float acc = (a0 + a1) + (a2 + a3);
        uint32_t m = spat[n];
#pragma unroll
        for (int t = 0; t < TT; t++)
            if ((m >> t) & 1u) I[t] += acc;
    }

    float thr = *thr_p;
    float memb = 0.f;
    int cnt = 0;
#pragma unroll
    for (int t = 0; t < TT; t++) {
        memb += I[t];
        if (memb > thr) { memb -= thr; cnt++; }
    }
    if (L == 0) g_cnt0[b * D0 + j] = cnt; else g_cnt2[b * D2OUT + j] = cnt;
}

// ---------------- pooling + layer-1 re-encoding (exact integer/pow2 arithmetic) ----------------
__global__ void mid_kernel(const int* __restrict__ idx1) {
    int b = blockIdx.x, p = threadIdx.x;
    int ch = p >> 4, oh = (p >> 2) & 3, ow = p & 3;
    int c = 0;
#pragma unroll
    for (int dh = 0; dh < 2; dh++)
#pragma unroll
        for (int dw = 0; dw < 2; dw++) {
            int k = ch * 64 + (2 * oh + dh) * 8 + (2 * ow + dw);
            c += g_cnt0[b * D0 + idx1[k]];
        }
    g_N1[b * D1 + p] = (unsigned char)__float2int_rn((float)c * 0.25f);
}

// ---------------- output gather ----------------
__global__ void out_kernel(const int* __restrict__ idx_out, float* __restrict__ out) {
    int b = blockIdx.x, j = threadIdx.x;
    if (j < D2OUT) out[b * D2OUT + j] = (float)g_cnt2[b * D2OUT + idx_out[j]];
}

// ---------------- launch ----------------
extern "C" void kernel_launch(void* const* d_in, const int* in_sizes, int n_in,
                              void* d_out, int out_size) {
    (void)in_sizes; (void)n_in; (void)out_size;
    const float* x       = (const float*)d_in[0];
    const float* w0      = (const float*)d_in[1];
    const float* t0      = (const float*)d_in[2];
    const float* w2      = (const float*)d_in[3];
    const float* t2      = (const float*)d_in[4];
    const int*   idx0    = (const int*)d_in[5];
    const int*   idx1    = (const int*)d_in[6];
    const int*   idx2    = (const int*)d_in[7];
    const int*   idx_out = (const int*)d_in[8];
    float* out = (float*)d_out;

    const int SMEM_TOTAL = 2 * 49152;   // 96 KB -> 2 CTAs/SM (R9's proven best regime)
    cudaFuncSetAttribute(gemm_lif_kernel<0>, cudaFuncAttributeMaxDynamicSharedMemorySize, SMEM_TOTAL);
    cudaFuncSetAttribute(gemm_lif_kernel<1>, cudaFuncAttributeMaxDynamicSharedMemorySize, SMEM_TOTAL);

    zero_kernel<<<1, 1>>>();
    split0_kernel<<<(int)(((size_t)D0 * D0) / 256), 256>>>(w0);
    split2_kernel<<<(D2OUT * D1) / 256, 256>>>(w2);

    buildA0_kernel<<<dim3(D0 / 256, BB), 256>>>(x, idx0);
    sort_kernel<D0><<<BB, 128>>>(x, idx0);
    gemm_lif_kernel<0><<<dim3(D0 / 128, MROWS / 128), 256, SMEM_TOTAL>>>(t0);
    compact_kernel<0><<<(BB * D0) / 256, 256>>>();
    fixup_kernel<0><<<(BB * D0) / 256, 256>>>(w0, t0);

    mid_kernel<<<BB, D1>>>(idx1);
    buildA2_kernel<<<dim3(D1 / 256, BB), 256>>>(idx2);
    sort_kernel<D1><<<BB, 128>>>(x, idx2);
    gemm_lif_kernel<1><<<dim3(D1 / 128, MROWS / 128), 256, SMEM_TOTAL>>>(t2);
    compact_kernel<1><<<(BB * D2OUT + 255) / 256, 256>>>();
    fixup_kernel<1><<<(BB * D2OUT + 255) / 256, 256>>>(w2, t2);

    out_kernel<<<BB, 1024>>>(idx_out, out);
}

// round 14
// speedup vs baseline: 1.7683x; 1.7683x over previous
#include <cuda_runtime.h>
#include <cuda_bf16.h>
#include <cstdint>
#include <math.h>

// ---------------- problem constants ----------------
#define BB     64
#define D0     4096
#define D1     1024
#define D2OUT  1000
#define TT     32
#define MROWS  (BB * TT)          // 2048 GEMM rows
#define DELTA  1e-3f              // borderline-gap threshold for exact fix-up

// ---------------- device scratch (static globals; no runtime alloc) ----------------
__device__ __nv_bfloat16 g_Bh[(size_t)D0 * D0];    // w0 hi split
__device__ __nv_bfloat16 g_Bm[(size_t)D0 * D0];    // w0 mid split
__device__ __nv_bfloat16 g_B2h[(size_t)D1 * D1];   // w2 splits; rows >= 1000 stay zero
__device__ __nv_bfloat16 g_B2m[(size_t)D1 * D1];
__device__ __nv_bfloat16 g_A[(size_t)MROWS * D0];  // spike matrix (ld 4096 L0 / 1024 L2)
__device__ int           g_cnt0[BB * D0];
__device__ unsigned char g_N1[BB * D1];
__device__ int           g_cnt2[BB * D2OUT];
__device__ unsigned char g_flag0[BB * D0];
__device__ unsigned char g_flag2[BB * D2OUT];
__device__ uint32_t      g_ord0[BB * D0];
__device__ uint32_t      g_inv0[BB * D0];          // inverse permutation: inv[i] = sorted pos
__device__ int           g_seg0[BB * 34];
__device__ uint32_t      g_ord2[BB * D1];
__device__ uint32_t      g_inv2[BB * D1];
__device__ int           g_seg2[BB * 34];
__device__ int           g_nwork0;                 // worklist sizes (zeroed each launch)
__device__ int           g_nwork2;
__device__ uint32_t      g_work0[BB * D0];         // packed flagged indices b*JMAX+j
__device__ uint32_t      g_work2[BB * D2OUT];

// ---------------- PTX helpers (base sm_103-legal only) ----------------
__device__ __forceinline__ uint32_t smem_u32(const void* p) {
    uint32_t a;
    asm("{ .reg .u64 t; cvta.to.shared.u64 t, %1; cvt.u32.u64 %0, t; }" : "=r"(a) : "l"(p));
    return a;
}
#define CP_ASYNC16(dst, src) \
    asm volatile("cp.async.cg.shared.global [%0], [%1], 16;" :: "r"(dst), "l"(src) : "memory")
#define CP_COMMIT() asm volatile("cp.async.commit_group;" ::: "memory")
#define CP_WAIT1()  asm volatile("cp.async.wait_group 1;" ::: "memory")
#define CP_WAIT0()  asm volatile("cp.async.wait_group 0;" ::: "memory")
#define LDSM4(r0, r1, r2, r3, addr)                                              \
    asm volatile("ldmatrix.sync.aligned.m8n8.x4.shared.b16 {%0,%1,%2,%3}, [%4];" \
                 : "=r"(r0), "=r"(r1), "=r"(r2), "=r"(r3) : "r"(addr))
#define MMA16816(d, a, b0, b1)                                                      \
    asm volatile("mma.sync.aligned.m16n8k16.row.col.f32.bf16.bf16.f32 "             \
                 "{%0,%1,%2,%3},{%4,%5,%6,%7},{%8,%9},{%0,%1,%2,%3};"               \
                 : "+f"((d)[0]), "+f"((d)[1]), "+f"((d)[2]), "+f"((d)[3])           \
                 : "r"((a)[0]), "r"((a)[1]), "r"((a)[2]), "r"((a)[3]),              \
                   "r"(b0), "r"(b1))
#define SWZ128(off) ((off) ^ (((off) >> 3) & 0x70))

// ---------------- uniform spike pattern (reference fp32 semantics) ----------------
__device__ __forceinline__ uint32_t pattern_mask(int n) {
    if (n <= 0)  return 0u;
    if (n >= TT) return 0xFFFFFFFFu;
    float spacing = __fdiv_rn(32.0f, (float)n);
    uint32_t m = 0u;
    for (int c = 0; c < TT; c++) {
        double r = fmod((double)c, (double)spacing);
        if (r < 1.0) m |= (1u << c);
    }
    return m;
}

// ---------------- weight splits: w = hi + mid (+ tiny residual handled by fix-up) ------
__global__ void split0_kernel(const float* __restrict__ w) {
    size_t idx = (size_t)blockIdx.x * 256 + threadIdx.x;
    float wv = w[idx];
    __nv_bfloat16 h = __float2bfloat16(wv);
    g_Bh[idx] = h; g_Bm[idx] = __float2bfloat16(wv - __bfloat162float(h));
}
__global__ void split2_kernel(const float* __restrict__ w) {
    size_t idx = (size_t)blockIdx.x * 256 + threadIdx.x;   // covers 1000*1024 exactly
    float wv = w[idx];
    __nv_bfloat16 h = __float2bfloat16(wv);
    g_B2h[idx] = h; g_B2m[idx] = __float2bfloat16(wv - __bfloat162float(h));
}

// ---------------- zero the worklist counters (fresh every launch) ----------------
__global__ void zero_kernel() { g_nwork0 = 0; g_nwork2 = 0; }

// ---------------- spike-matrix builds (bf16 {0,1}) ----------------
__global__ void buildA0_kernel(const float* __restrict__ x, const int* __restrict__ idx0) {
    __shared__ uint32_t spat[33];
    int tid = threadIdx.x;
    if (tid < 33) spat[tid] = pattern_mask(tid);
    __syncthreads();
    int b = blockIdx.y;
    int i = blockIdx.x * 256 + tid;
    float r = x[b * D0 + idx0[i]];
    uint32_t m = spat[__float2int_rn(r * 32.0f)];
    unsigned short* A = (unsigned short*)g_A;
#pragma unroll
    for (int t = 0; t < TT; t++)
        A[(size_t)(b * TT + t) * D0 + i] = ((m >> t) & 1u) ? (unsigned short)0x3F80 : (unsigned short)0;
}
__global__ void buildA2_kernel(const int* __restrict__ idx2) {
    __shared__ uint32_t spat[33];
    int tid = threadIdx.x;
    if (tid < 33) spat[tid] = pattern_mask(tid);
    __syncthreads();
    int b = blockIdx.y;
    int i = blockIdx.x * 256 + tid;
    uint32_t m = spat[g_N1[b * D1 + idx2[i]]];
    unsigned short* A = (unsigned short*)g_A;
#pragma unroll
    for (int t = 0; t < TT; t++)
        A[(size_t)(b * TT + t) * D1 + i] = ((m >> t) & 1u) ? (unsigned short)0x3F80 : (unsigned short)0;
}

// ---------------- deterministic bucket sort (spill-free; identical ord/seg to R1) ----------
// Also emits the inverse permutation inv[i] = position of i in the sorted order.
template <int K>
__global__ void sort_kernel(const float* __restrict__ x, const int* __restrict__ idxg) {
    __shared__ unsigned char ns[K];
    __shared__ int cnt[128 * 33];
    __shared__ int base[34];
    int b = blockIdx.x, t = threadIdx.x;
    constexpr int CH = K / 128;

    if (K == D0) {
        for (int i = t; i < K; i += 128)
            ns[i] = (unsigned char)__float2int_rn(x[b * D0 + idxg[i]] * 32.0f);
    } else {
        for (int i = t; i < K; i += 128)
            ns[i] = g_N1[b * D1 + idxg[i]];
    }
#pragma unroll
    for (int n = 0; n < 33; n++) cnt[t * 33 + n] = 0;
    __syncthreads();
    for (int c = 0; c < CH; c++) cnt[t * 33 + ns[t * CH + c]]++;
    __syncthreads();
    if (t < 33) {
        int run = 0;
        for (int u = 0; u < 128; u++) { int v = cnt[u * 33 + t]; cnt[u * 33 + t] = run; run += v; }
        base[t] = run;
    }
    __syncthreads();
    if (t == 0) {
        int acc = 0;
        for (int n = 0; n < 33; n++) { int v = base[n]; base[n] = acc; acc += v; }
        base[33] = acc;
    }
    __syncthreads();
    uint32_t* ord = ((K == D0) ? g_ord0 : g_ord2) + (size_t)b * K;
    uint32_t* inv = ((K == D0) ? g_inv0 : g_inv2) + (size_t)b * K;
    int* seg = ((K == D0) ? g_seg0 : g_seg2) + b * 34;
    for (int c = 0; c < CH; c++) {
        int i = t * CH + c;
        int n = ns[i];
        int pos = base[n] + cnt[t * 33 + n];
        cnt[t * 33 + n]++;
        ord[pos] = (uint32_t)i;
        inv[i] = (uint32_t)pos;
    }
    if (t < 34) seg[t] = base[t];
}

// ---------------- GEMM (2 bf16 splits) + fused LIF scan + borderline flagging ----------
// Exact R9 configuration: block 128x128, warp 32x64, K-chunk 64, 2-stage, 2 CTAs/SM.
template <int L>
__global__ void __launch_bounds__(256, 2) gemm_lif_kernel(const float* __restrict__ thr_p) {
    constexpr int KTOT = (L == 0) ? D0 : D1;
    constexpr int NC   = KTOT / 64;
    constexpr int JMAX = (L == 0) ? D0 : D2OUT;
    constexpr uint32_t STAGE = 49152u;   // A(16K) + Bh(16K) + Bm(16K)

    extern __shared__ char smem[];
    uint32_t sb = smem_u32(smem);
    int tid = threadIdx.x, wid = tid >> 5, lane = tid & 31;
    int n0 = blockIdx.x * 128, m0 = blockIdx.y * 128;
    int wm = wid >> 1, wn = wid & 1;
    const int mW = wm * 32, nW = wn * 64;

    const __nv_bfloat16* Bs[2];
    if (L == 0) { Bs[0] = g_Bh; Bs[1] = g_Bm; }
    else        { Bs[0] = g_B2h; Bs[1] = g_B2m; }

    auto load_stage = [&](int stage, int kc) {
        uint32_t st = sb + (uint32_t)stage * STAGE;
        int k0 = kc * 64;
#pragma unroll
        for (int u = 0; u < 4; u++) {
            int slot = u * 256 + tid, r = slot >> 3, kk = slot & 7;
            const __nv_bfloat16* gp = g_A + (size_t)(m0 + r) * KTOT + k0 + kk * 8;
            CP_ASYNC16(st + SWZ128((uint32_t)(r * 128 + kk * 16)), gp);
        }
#pragma unroll
        for (int s = 0; s < 2; s++) {
            uint32_t bb = st + 16384u * (1 + s);
#pragma unroll
            for (int u = 0; u < 4; u++) {
                int slot = u * 256 + tid, r = slot >> 3, kk = slot & 7;
                const __nv_bfloat16* gp = Bs[s] + (size_t)(n0 + r) * KTOT + k0 + kk * 8;
                CP_ASYNC16(bb + SWZ128((uint32_t)(r * 128 + kk * 16)), gp);
            }
        }
        CP_COMMIT();
    };

    float acc[2][8][4];
#pragma unroll
    for (int a = 0; a < 2; a++)
#pragma unroll
        for (int b = 0; b < 8; b++)
#pragma unroll
            for (int c = 0; c < 4; c++) acc[a][b][c] = 0.f;

    int q = lane >> 3, w8 = lane & 7;

    load_stage(0, 0);
#pragma unroll 1
    for (int c = 0; c < NC; c++) {
        if (c + 1 < NC) { load_stage((c + 1) & 1, c + 1); CP_WAIT1(); }
        else            { CP_WAIT0(); }
        __syncthreads();

        uint32_t st = sb + (uint32_t)(c & 1) * STAGE;
#pragma unroll
        for (int ks = 0; ks < 4; ks++) {
            uint32_t af[2][4];
#pragma unroll
            for (int mf = 0; mf < 2; mf++) {
                int row = mW + mf * 16 + w8 + (q & 1) * 8;
                int colb = ks * 32 + (q >> 1) * 16;
                LDSM4(af[mf][0], af[mf][1], af[mf][2], af[mf][3],
                      st + SWZ128((uint32_t)(row * 128 + colb)));
            }
#pragma unroll
            for (int s = 0; s < 2; s++) {
                uint32_t bbase = st + 16384u * (1 + s);
#pragma unroll
                for (int nfp = 0; nfp < 4; nfp++) {
                    uint32_t b0, b1, b2, b3;
                    int row = nW + nfp * 16 + w8 + (q >> 1) * 8;
                    int colb = ks * 32 + (q & 1) * 16;
                    LDSM4(b0, b1, b2, b3, bbase + SWZ128((uint32_t)(row * 128 + colb)));
                    MMA16816(acc[0][2 * nfp + 0], af[0], b0, b1);
                    MMA16816(acc[0][2 * nfp + 1], af[0], b2, b3);
                    MMA16816(acc[1][2 * nfp + 0], af[1], b0, b1);
                    MMA16816(acc[1][2 * nfp + 1], af[1], b2, b3);
                }
            }
        }
        __syncthreads();
    }

    // ---- epilogue: transpose C through padded smem tile, LIF scan + gap flag ----
    float* ct = (float*)smem;                         // [128][129] fp32 (66 KB < 96 KB)
#pragma unroll
    for (int mf = 0; mf < 2; mf++)
#pragma unroll
        for (int nf = 0; nf < 8; nf++) {
            int row = mW + mf * 16 + (lane >> 2);
            int col = nW + nf * 8 + 2 * (lane & 3);
            ct[row * 129 + col]           = acc[mf][nf][0];
            ct[row * 129 + col + 1]       = acc[mf][nf][1];
            ct[(row + 8) * 129 + col]     = acc[mf][nf][2];
            ct[(row + 8) * 129 + col + 1] = acc[mf][nf][3];
        }
    __syncthreads();

    float thr = *thr_p;
    int* cnt_out = (L == 0) ? g_cnt0 : g_cnt2;
    unsigned char* flag_out = (L == 0) ? g_flag0 : g_flag2;
#pragma unroll
    for (int pp = 0; pp < 2; pp++) {
        int p = pp * 256 + tid;
        int bl = p >> 7, j = p & 127;
        float memb = 0.f, ming = 1e30f;
        int cnt = 0;
#pragma unroll
        for (int t = 0; t < TT; t++) {
            memb += ct[(bl * 32 + t) * 129 + j];
            float g = fabsf(memb - thr);
            if (g < ming) ming = g;
            if (memb > thr) { memb -= thr; cnt++; }
        }
        int bglob = blockIdx.y * 4 + bl;
        int jglob = n0 + j;
        if (jglob < JMAX) {
            cnt_out[(size_t)bglob * JMAX + jglob] = cnt;
            flag_out[(size_t)bglob * JMAX + jglob] = (ming < DELTA) ? 1 : 0;
        }
    }
}

// ---------------- worklist compaction (order-independent results; atomics OK) ----------
template <int L>
__global__ void compact_kernel() {
    constexpr int JMAX = (L == 0) ? D0 : D2OUT;
    int idx = blockIdx.x * 256 + threadIdx.x;
    if (idx >= BB * JMAX) return;
    if (((L == 0) ? g_flag0 : g_flag2)[idx]) {
        int p = atomicAdd((L == 0) ? &g_nwork0 : &g_nwork2, 1);
        ((L == 0) ? g_work0 : g_work2)[p] = (uint32_t)idx;
    }
}

// ---------------- exact fix-up: warp-per-row, coalesced gather to smem, serial consume ----
// 32 lanes read the weight row contiguously and scatter into sw[] at the sorted position
// (sw ends up holding values in exactly R1's po order). Lane 0 then performs the
// byte-identical R1/R9 add sequence + LIF scan. Same values, same order => bit-exact.
template <int L>
__global__ void __launch_bounds__(32) fixup_kernel(const float* __restrict__ w,
                                                   const float* __restrict__ thr_p) {
    constexpr int K    = (L == 0) ? D0 : D1;
    constexpr int JMAX = (L == 0) ? D0 : D2OUT;
    extern __shared__ float sw[];                 // K floats
    __shared__ uint32_t spat[33];
    int lane = threadIdx.x;
    for (int n = lane; n < 33; n += 32) spat[n] = pattern_mask(n);
    __syncwarp();

    int nwork = (L == 0) ? g_nwork0 : g_nwork2;
    const uint32_t* work = (L == 0) ? g_work0 : g_work2;
    float thr = *thr_p;

    for (int wi = blockIdx.x; wi < nwork; wi += gridDim.x) {
        int idx = (int)work[wi];
        int b = idx / JMAX, j = idx % JMAX;
        const uint32_t* inv = ((L == 0) ? g_inv0 : g_inv2) + (size_t)b * K;
        const float* wrow = w + (size_t)j * K;

        // coalesced gather: contiguous global reads, smem scatter to sorted position
#pragma unroll 4
        for (int i = lane; i < K; i += 32) sw[inv[i]] = wrow[i];
        __syncwarp();

        if (lane == 0) {
            const int* sg = ((L == 0) ? g_seg0 : g_seg2) + b * 34;
            float I[TT];
#pragma unroll
            for (int t = 0; t < TT; t++) I[t] = 0.f;

#pragma unroll 1
            for (int n = 1; n < 33; n++) {
                int s = sg[n], e = sg[n + 1];
                if (s >= e) continue;
                float a0 = 0.f, a1 = 0.f, a2 = 0.f, a3 = 0.f;
                int k = s;
                float p0 = 0.f, p1 = 0.f, p2 = 0.f, p3 = 0.f;
                if (k + 4 <= e) { p0 = sw[k]; p1 = sw[k + 1]; p2 = sw[k + 2]; p3 = sw[k + 3]; }
#pragma unroll 1
                for (; k + 4 <= e; ) {
                    float c0 = p0, c1 = p1, c2 = p2, c3 = p3;
                    int kn = k + 4;
                    if (kn + 4 <= e) { p0 = sw[kn]; p1 = sw[kn + 1]; p2 = sw[kn + 2]; p3 = sw[kn + 3]; }
                    a0 += c0; a1 += c1; a2 += c2; a3 += c3;   // R1 add order
                    k = kn;
                }
                for (; k < e; k++) a0 += sw[k];
                float acc = (a0 + a1) + (a2 + a3);
                uint32_t m = spat[n];
#pragma unroll
                for (int t = 0; t < TT; t++)
                    if ((m >> t) & 1u) I[t] += acc;
            }

            float memb = 0.f;
            int cnt = 0;
#pragma unroll
            for (int t = 0; t < TT; t++) {
                memb += I[t];
                if (memb > thr) { memb -= thr; cnt++; }
            }
            if (L == 0) g_cnt0[b * D0 + j] = cnt; else g_cnt2[b * D2OUT + j] = cnt;
        }
        __syncwarp();
    }
}

// ---------------- pooling + layer-1 re-encoding (exact integer/pow2 arithmetic) ----------------
__global__ void mid_kernel(const int* __restrict__ idx1) {
    int b = blockIdx.x, p = threadIdx.x;
    int ch = p >> 4, oh = (p >> 2) & 3, ow = p & 3;
    int c = 0;
#pragma unroll
    for (int dh = 0; dh < 2; dh++)
#pragma unroll
        for (int dw = 0; dw < 2; dw++) {
            int k = ch * 64 + (2 * oh + dh) * 8 + (2 * ow + dw);
            c += g_cnt0[b * D0 + idx1[k]];
        }
    g_N1[b * D1 + p] = (unsigned char)__float2int_rn((float)c * 0.25f);
}

// ---------------- output gather ----------------
__global__ void out_kernel(const int* __restrict__ idx_out, float* __restrict__ out) {
    int b = blockIdx.x, j = threadIdx.x;
    if (j < D2OUT) out[b * D2OUT + j] = (float)g_cnt2[b * D2OUT + idx_out[j]];
}

// ---------------- launch ----------------
extern "C" void kernel_launch(void* const* d_in, const int* in_sizes, int n_in,
                              void* d_out, int out_size) {
    (void)in_sizes; (void)n_in; (void)out_size;
    const float* x       = (const float*)d_in[0];
    const float* w0      = (const float*)d_in[1];
    const float* t0      = (const float*)d_in[2];
    const float* w2      = (const float*)d_in[3];
    const float* t2      = (const float*)d_in[4];
    const int*   idx0    = (const int*)d_in[5];
    const int*   idx1    = (const int*)d_in[6];
    const int*   idx2    = (const int*)d_in[7];
    const int*   idx_out = (const int*)d_in[8];
    float* out = (float*)d_out;

    const int SMEM_TOTAL = 2 * 49152;   // 96 KB -> 2 CTAs/SM (R9's proven best regime)
    cudaFuncSetAttribute(gemm_lif_kernel<0>, cudaFuncAttributeMaxDynamicSharedMemorySize, SMEM_TOTAL);
    cudaFuncSetAttribute(gemm_lif_kernel<1>, cudaFuncAttributeMaxDynamicSharedMemorySize, SMEM_TOTAL);

    zero_kernel<<<1, 1>>>();
    split0_kernel<<<(int)(((size_t)D0 * D0) / 256), 256>>>(w0);
    split2_kernel<<<(D2OUT * D1) / 256, 256>>>(w2);

    buildA0_kernel<<<dim3(D0 / 256, BB), 256>>>(x, idx0);
    sort_kernel<D0><<<BB, 128>>>(x, idx0);
    gemm_lif_kernel<0><<<dim3(D0 / 128, MROWS / 128), 256, SMEM_TOTAL>>>(t0);
    compact_kernel<0><<<(BB * D0) / 256, 256>>>();
    fixup_kernel<0><<<2048, 32, D0 * 4>>>(w0, t0);

    mid_kernel<<<BB, D1>>>(idx1);
    buildA2_kernel<<<dim3(D1 / 256, BB), 256>>>(idx2);
    sort_kernel<D1><<<BB, 128>>>(x, idx2);
    gemm_lif_kernel<1><<<dim3(D1 / 128, MROWS / 128), 256, SMEM_TOTAL>>>(t2);
    compact_kernel<1><<<(BB * D2OUT + 255) / 256, 256>>>();
    fixup_kernel<1><<<512, 32, D1 * 4>>>(w2, t2);

    out_kernel<<<BB, 1024>>>(idx_out, out);
}

// round 15
// speedup vs baseline: 1.7834x; 1.0086x over previous
#include <cuda_runtime.h>
#include <cuda_bf16.h>
#include <cstdint>
#include <math.h>

// ---------------- problem constants ----------------
#define BB     64
#define D0     4096
#define D1     1024
#define D2OUT  1000
#define TT     32
#define MROWS  (BB * TT)          // 2048 GEMM rows
#define DELTA  1e-3f              // borderline-gap threshold for exact fix-up

// ---------------- device scratch (static globals; no runtime alloc) ----------------
__device__ __nv_bfloat16 g_Bh[(size_t)D0 * D0];    // w0 hi split
__device__ __nv_bfloat16 g_Bm[(size_t)D0 * D0];    // w0 mid split
__device__ __nv_bfloat16 g_B2h[(size_t)D1 * D1];   // w2 splits; rows >= 1000 stay zero
__device__ __nv_bfloat16 g_B2m[(size_t)D1 * D1];
__device__ __nv_bfloat16 g_A[(size_t)MROWS * D0];  // spike matrix (ld 4096 L0 / 1024 L2)
__device__ int           g_cnt0[BB * D0];
__device__ unsigned char g_N1[BB * D1];
__device__ int           g_cnt2[BB * D2OUT];
__device__ uint32_t      g_ord0[BB * D0];
__device__ uint32_t      g_inv0[BB * D0];          // inverse permutation: inv[i] = sorted pos
__device__ int           g_seg0[BB * 34];
__device__ uint32_t      g_ord2[BB * D1];
__device__ uint32_t      g_inv2[BB * D1];
__device__ int           g_seg2[BB * 34];
__device__ int           g_nwork0;                 // worklist sizes (zeroed in buildA0)
__device__ int           g_nwork2;
__device__ uint32_t      g_work0[BB * D0];         // packed flagged indices b*JMAX+j
__device__ uint32_t      g_work2[BB * D2OUT];

// ---------------- PTX helpers (base sm_103-legal only) ----------------
__device__ __forceinline__ uint32_t smem_u32(const void* p) {
    uint32_t a;
    asm("{ .reg .u64 t; cvta.to.shared.u64 t, %1; cvt.u32.u64 %0, t; }" : "=r"(a) : "l"(p));
    return a;
}
#define CP_ASYNC16(dst, src) \
    asm volatile("cp.async.cg.shared.global [%0], [%1], 16;" :: "r"(dst), "l"(src) : "memory")
#define CP_COMMIT() asm volatile("cp.async.commit_group;" ::: "memory")
#define CP_WAIT1()  asm volatile("cp.async.wait_group 1;" ::: "memory")
#define CP_WAIT0()  asm volatile("cp.async.wait_group 0;" ::: "memory")
#define LDSM4(r0, r1, r2, r3, addr)                                              \
    asm volatile("ldmatrix.sync.aligned.m8n8.x4.shared.b16 {%0,%1,%2,%3}, [%4];" \
                 : "=r"(r0), "=r"(r1), "=r"(r2), "=r"(r3) : "r"(addr))
#define MMA16816(d, a, b0, b1)                                                      \
    asm volatile("mma.sync.aligned.m16n8k16.row.col.f32.bf16.bf16.f32 "             \
                 "{%0,%1,%2,%3},{%4,%5,%6,%7},{%8,%9},{%0,%1,%2,%3};"               \
                 : "+f"((d)[0]), "+f"((d)[1]), "+f"((d)[2]), "+f"((d)[3])           \
                 : "r"((a)[0]), "r"((a)[1]), "r"((a)[2]), "r"((a)[3]),              \
                   "r"(b0), "r"(b1))
#define SWZ128(off) ((off) ^ (((off) >> 3) & 0x70))

// ---------------- uniform spike pattern (reference fp32 semantics) ----------------
__device__ __forceinline__ uint32_t pattern_mask(int n) {
    if (n <= 0)  return 0u;
    if (n >= TT) return 0xFFFFFFFFu;
    float spacing = __fdiv_rn(32.0f, (float)n);
    uint32_t m = 0u;
    for (int c = 0; c < TT; c++) {
        double r = fmod((double)c, (double)spacing);
        if (r < 1.0) m |= (1u << c);
    }
    return m;
}

// ---------------- weight splits: w = hi + mid (+ tiny residual handled by fix-up) ------
__global__ void split0_kernel(const float* __restrict__ w) {
    size_t idx = (size_t)blockIdx.x * 256 + threadIdx.x;
    float wv = w[idx];
    __nv_bfloat16 h = __float2bfloat16(wv);
    g_Bh[idx] = h; g_Bm[idx] = __float2bfloat16(wv - __bfloat162float(h));
}
__global__ void split2_kernel(const float* __restrict__ w) {
    size_t idx = (size_t)blockIdx.x * 256 + threadIdx.x;   // covers 1000*1024 exactly
    float wv = w[idx];
    __nv_bfloat16 h = __float2bfloat16(wv);
    g_B2h[idx] = h; g_B2m[idx] = __float2bfloat16(wv - __bfloat162float(h));
}

// ---------------- spike-matrix build, layer 0 (4 i's per thread, 64-bit stores) --------
// Also zeroes the worklist counters (runs before both GEMMs in stream order).
__global__ void buildA0_kernel(const float* __restrict__ x, const int* __restrict__ idx0) {
    __shared__ uint32_t spat[33];
    int tid = threadIdx.x;
    if (tid < 33) spat[tid] = pattern_mask(tid);
    if (blockIdx.x == 0 && blockIdx.y == 0 && tid == 0) { g_nwork0 = 0; g_nwork2 = 0; }
    __syncthreads();
    int b = blockIdx.y;
    int i0 = blockIdx.x * 1024 + tid * 4;
    uint32_t m0 = spat[__float2int_rn(x[b * D0 + idx0[i0 + 0]] * 32.0f)];
    uint32_t m1 = spat[__float2int_rn(x[b * D0 + idx0[i0 + 1]] * 32.0f)];
    uint32_t m2 = spat[__float2int_rn(x[b * D0 + idx0[i0 + 2]] * 32.0f)];
    uint32_t m3 = spat[__float2int_rn(x[b * D0 + idx0[i0 + 3]] * 32.0f)];
#pragma unroll
    for (int t = 0; t < TT; t++) {
        uint64_t v = (uint64_t)(((m0 >> t) & 1u) * 0x3F80u)
                   | ((uint64_t)(((m1 >> t) & 1u) * 0x3F80u) << 16)
                   | ((uint64_t)(((m2 >> t) & 1u) * 0x3F80u) << 32)
                   | ((uint64_t)(((m3 >> t) & 1u) * 0x3F80u) << 48);
        *(uint64_t*)((unsigned short*)g_A + (size_t)(b * TT + t) * D0 + i0) = v;
    }
}

// ---------------- deterministic bucket sort, layer 0 (identical ord/seg/inv to R14) -----
__global__ void sort0_kernel(const float* __restrict__ x, const int* __restrict__ idxg) {
    __shared__ unsigned char ns[D0];
    __shared__ int cnt[128 * 33];
    __shared__ int base[34];
    int b = blockIdx.x, t = threadIdx.x;
    constexpr int CH = D0 / 128;

    for (int i = t; i < D0; i += 128)
        ns[i] = (unsigned char)__float2int_rn(x[b * D0 + idxg[i]] * 32.0f);
#pragma unroll
    for (int n = 0; n < 33; n++) cnt[t * 33 + n] = 0;
    __syncthreads();
    for (int c = 0; c < CH; c++) cnt[t * 33 + ns[t * CH + c]]++;
    __syncthreads();
    if (t < 33) {
        int run = 0;
        for (int u = 0; u < 128; u++) { int v = cnt[u * 33 + t]; cnt[u * 33 + t] = run; run += v; }
        base[t] = run;
    }
    __syncthreads();
    if (t == 0) {
        int acc = 0;
        for (int n = 0; n < 33; n++) { int v = base[n]; base[n] = acc; acc += v; }
        base[33] = acc;
    }
    __syncthreads();
    uint32_t* ord = g_ord0 + (size_t)b * D0;
    uint32_t* inv = g_inv0 + (size_t)b * D0;
    for (int c = 0; c < CH; c++) {
        int i = t * CH + c;
        int n = ns[i];
        int pos = base[n] + cnt[t * 33 + n];
        cnt[t * 33 + n]++;
        ord[pos] = (uint32_t)i;
        inv[i] = (uint32_t)pos;
    }
    if (t < 34) g_seg0[b * 34 + t] = base[t];
}

// ---------------- GEMM (2 bf16 splits) + fused LIF scan + direct worklist append -------
// Exact R9/R14 configuration: block 128x128, warp 32x64, K-chunk 64, 2-stage, 2 CTAs/SM.
template <int L>
__global__ void __launch_bounds__(256, 2) gemm_lif_kernel(const float* __restrict__ thr_p) {
    constexpr int KTOT = (L == 0) ? D0 : D1;
    constexpr int NC   = KTOT / 64;
    constexpr int JMAX = (L == 0) ? D0 : D2OUT;
    constexpr uint32_t STAGE = 49152u;   // A(16K) + Bh(16K) + Bm(16K)

    extern __shared__ char smem[];
    uint32_t sb = smem_u32(smem);
    int tid = threadIdx.x, wid = tid >> 5, lane = tid & 31;
    int n0 = blockIdx.x * 128, m0 = blockIdx.y * 128;
    int wm = wid >> 1, wn = wid & 1;
    const int mW = wm * 32, nW = wn * 64;

    const __nv_bfloat16* Bs[2];
    if (L == 0) { Bs[0] = g_Bh; Bs[1] = g_Bm; }
    else        { Bs[0] = g_B2h; Bs[1] = g_B2m; }

    auto load_stage = [&](int stage, int kc) {
        uint32_t st = sb + (uint32_t)stage * STAGE;
        int k0 = kc * 64;
#pragma unroll
        for (int u = 0; u < 4; u++) {
            int slot = u * 256 + tid, r = slot >> 3, kk = slot & 7;
            const __nv_bfloat16* gp = g_A + (size_t)(m0 + r) * KTOT + k0 + kk * 8;
            CP_ASYNC16(st + SWZ128((uint32_t)(r * 128 + kk * 16)), gp);
        }
#pragma unroll
        for (int s = 0; s < 2; s++) {
            uint32_t bb = st + 16384u * (1 + s);
#pragma unroll
            for (int u = 0; u < 4; u++) {
                int slot = u * 256 + tid, r = slot >> 3, kk = slot & 7;
                const __nv_bfloat16* gp = Bs[s] + (size_t)(n0 + r) * KTOT + k0 + kk * 8;
                CP_ASYNC16(bb + SWZ128((uint32_t)(r * 128 + kk * 16)), gp);
            }
        }
        CP_COMMIT();
    };

    float acc[2][8][4];
#pragma unroll
    for (int a = 0; a < 2; a++)
#pragma unroll
        for (int b = 0; b < 8; b++)
#pragma unroll
            for (int c = 0; c < 4; c++) acc[a][b][c] = 0.f;

    int q = lane >> 3, w8 = lane & 7;

    load_stage(0, 0);
#pragma unroll 1
    for (int c = 0; c < NC; c++) {
        if (c + 1 < NC) { load_stage((c + 1) & 1, c + 1); CP_WAIT1(); }
        else            { CP_WAIT0(); }
        __syncthreads();

        uint32_t st = sb + (uint32_t)(c & 1) * STAGE;
#pragma unroll
        for (int ks = 0; ks < 4; ks++) {
            uint32_t af[2][4];
#pragma unroll
            for (int mf = 0; mf < 2; mf++) {
                int row = mW + mf * 16 + w8 + (q & 1) * 8;
                int colb = ks * 32 + (q >> 1) * 16;
                LDSM4(af[mf][0], af[mf][1], af[mf][2], af[mf][3],
                      st + SWZ128((uint32_t)(row * 128 + colb)));
            }
#pragma unroll
            for (int s = 0; s < 2; s++) {
                uint32_t bbase = st + 16384u * (1 + s);
#pragma unroll
                for (int nfp = 0; nfp < 4; nfp++) {
                    uint32_t b0, b1, b2, b3;
                    int row = nW + nfp * 16 + w8 + (q >> 1) * 8;
                    int colb = ks * 32 + (q & 1) * 16;
                    LDSM4(b0, b1, b2, b3, bbase + SWZ128((uint32_t)(row * 128 + colb)));
                    MMA16816(acc[0][2 * nfp + 0], af[0], b0, b1);
                    MMA16816(acc[0][2 * nfp + 1], af[0], b2, b3);
                    MMA16816(acc[1][2 * nfp + 0], af[1], b0, b1);
                    MMA16816(acc[1][2 * nfp + 1], af[1], b2, b3);
                }
            }
        }
        __syncthreads();
    }

    // ---- epilogue: transpose C through padded smem tile, LIF scan + worklist append ----
    float* ct = (float*)smem;                         // [128][129] fp32 (66 KB < 96 KB)
#pragma unroll
    for (int mf = 0; mf < 2; mf++)
#pragma unroll
        for (int nf = 0; nf < 8; nf++) {
            int row = mW + mf * 16 + (lane >> 2);
            int col = nW + nf * 8 + 2 * (lane & 3);
            ct[row * 129 + col]           = acc[mf][nf][0];
            ct[row * 129 + col + 1]       = acc[mf][nf][1];
            ct[(row + 8) * 129 + col]     = acc[mf][nf][2];
            ct[(row + 8) * 129 + col + 1] = acc[mf][nf][3];
        }
    __syncthreads();

    float thr = *thr_p;
    int* cnt_out = (L == 0) ? g_cnt0 : g_cnt2;
#pragma unroll
    for (int pp = 0; pp < 2; pp++) {
        int p = pp * 256 + tid;
        int bl = p >> 7, j = p & 127;
        float memb = 0.f, ming = 1e30f;
        int cnt = 0;
#pragma unroll
        for (int t = 0; t < TT; t++) {
            memb += ct[(bl * 32 + t) * 129 + j];
            float g = fabsf(memb - thr);
            if (g < ming) ming = g;
            if (memb > thr) { memb -= thr; cnt++; }
        }
        int bglob = blockIdx.y * 4 + bl;
        int jglob = n0 + j;
        if (jglob < JMAX) {
            cnt_out[(size_t)bglob * JMAX + jglob] = cnt;
            if (ming < DELTA) {   // direct worklist append (order-independent results)
                int pos = atomicAdd((L == 0) ? &g_nwork0 : &g_nwork2, 1);
                ((L == 0) ? g_work0 : g_work2)[pos] = (uint32_t)(bglob * JMAX + jglob);
            }
        }
    }
}

// ---------------- exact fix-up: warp-per-row, coalesced gather to smem, serial consume ----
// Byte-identical value/add order to the thrice-verified R1 path.
template <int L>
__global__ void __launch_bounds__(32) fixup_kernel(const float* __restrict__ w,
                                                   const float* __restrict__ thr_p) {
    constexpr int K    = (L == 0) ? D0 : D1;
    constexpr int JMAX = (L == 0) ? D0 : D2OUT;
    extern __shared__ float sw[];                 // K floats
    __shared__ uint32_t spat[33];
    int lane = threadIdx.x;
    for (int n = lane; n < 33; n += 32) spat[n] = pattern_mask(n);
    __syncwarp();

    int nwork = (L == 0) ? g_nwork0 : g_nwork2;
    const uint32_t* work = (L == 0) ? g_work0 : g_work2;
    float thr = *thr_p;

    for (int wi = blockIdx.x; wi < nwork; wi += gridDim.x) {
        int idx = (int)work[wi];
        int b = idx / JMAX, j = idx % JMAX;
        const uint32_t* inv = ((L == 0) ? g_inv0 : g_inv2) + (size_t)b * K;
        const float* wrow = w + (size_t)j * K;

#pragma unroll 4
        for (int i = lane; i < K; i += 32) sw[inv[i]] = wrow[i];
        __syncwarp();

        if (lane == 0) {
            const int* sg = ((L == 0) ? g_seg0 : g_seg2) + b * 34;
            float I[TT];
#pragma unroll
            for (int t = 0; t < TT; t++) I[t] = 0.f;

#pragma unroll 1
            for (int n = 1; n < 33; n++) {
                int s = sg[n], e = sg[n + 1];
                if (s >= e) continue;
                float a0 = 0.f, a1 = 0.f, a2 = 0.f, a3 = 0.f;
                int k = s;
                float p0 = 0.f, p1 = 0.f, p2 = 0.f, p3 = 0.f;
                if (k + 4 <= e) { p0 = sw[k]; p1 = sw[k + 1]; p2 = sw[k + 2]; p3 = sw[k + 3]; }
#pragma unroll 1
                for (; k + 4 <= e; ) {
                    float c0 = p0, c1 = p1, c2 = p2, c3 = p3;
                    int kn = k + 4;
                    if (kn + 4 <= e) { p0 = sw[kn]; p1 = sw[kn + 1]; p2 = sw[kn + 2]; p3 = sw[kn + 3]; }
                    a0 += c0; a1 += c1; a2 += c2; a3 += c3;   // R1 add order
                    k = kn;
                }
                for (; k < e; k++) a0 += sw[k];
                float acc = (a0 + a1) + (a2 + a3);
                uint32_t m = spat[n];
#pragma unroll
                for (int t = 0; t < TT; t++)
                    if ((m >> t) & 1u) I[t] += acc;
            }

            float memb = 0.f;
            int cnt = 0;
#pragma unroll
            for (int t = 0; t < TT; t++) {
                memb += I[t];
                if (memb > thr) { memb -= thr; cnt++; }
            }
            if (L == 0) g_cnt0[b * D0 + j] = cnt; else g_cnt2[b * D2OUT + j] = cnt;
        }
        __syncwarp();
    }
}

// ---------------- fused middle stage: pooling + re-encode + buildA2 + sort2 ------------
// One block per batch, 1024 threads. Phases separated by __syncthreads (global writes
// within a block are ordered by __syncthreads). Sort phase: identical chunked counting
// sort (threads < 128) -> bit-identical ord2/seg2/inv2.
__global__ void mid_kernel(const int* __restrict__ idx1, const int* __restrict__ idx2) {
    __shared__ uint32_t spat[33];
    __shared__ unsigned char ns[D1];
    __shared__ int cnt[128 * 33];
    __shared__ int base[34];
    int b = blockIdx.x, t = threadIdx.x;

    if (t < 33) spat[t] = pattern_mask(t);

    // phase 1: avg-pool spike counts -> N1 (exact integer/pow2 arithmetic)
    {
        int p = t;   // 0..1023
        int ch = p >> 4, oh = (p >> 2) & 3, ow = p & 3;
        int c = 0;
#pragma unroll
        for (int dh = 0; dh < 2; dh++)
#pragma unroll
            for (int dw = 0; dw < 2; dw++) {
                int k = ch * 64 + (2 * oh + dh) * 8 + (2 * ow + dw);
                c += g_cnt0[b * D0 + idx1[k]];
            }
        g_N1[b * D1 + p] = (unsigned char)__float2int_rn((float)c * 0.25f);
    }
    __syncthreads();

    // phase 2: gather bucket ids through idx2 + build A2 (4 i's per thread, u64 stores)
    if (t < 256) {
        int i0 = t * 4;
        uint32_t m0 = spat[g_N1[b * D1 + idx2[i0 + 0]]];
        uint32_t m1 = spat[g_N1[b * D1 + idx2[i0 + 1]]];
        uint32_t m2 = spat[g_N1[b * D1 + idx2[i0 + 2]]];
        uint32_t m3 = spat[g_N1[b * D1 + idx2[i0 + 3]]];
#pragma unroll
        for (int tt = 0; tt < TT; tt++) {
            uint64_t v = (uint64_t)(((m0 >> tt) & 1u) * 0x3F80u)
                       | ((uint64_t)(((m1 >> tt) & 1u) * 0x3F80u) << 16)
                       | ((uint64_t)(((m2 >> tt) & 1u) * 0x3F80u) << 32)
                       | ((uint64_t)(((m3 >> tt) & 1u) * 0x3F80u) << 48);
            *(uint64_t*)((unsigned short*)g_A + (size_t)(b * TT + tt) * D1 + i0) = v;
        }
    }
    // stage ns for the sort (all 1024 threads)
    ns[t] = g_N1[b * D1 + idx2[t]];
    __syncthreads();

    // phase 3: counting sort (threads < 128), CH = 8
    constexpr int CH = D1 / 128;
    if (t < 128) {
#pragma unroll
        for (int n = 0; n < 33; n++) cnt[t * 33 + n] = 0;
        for (int c = 0; c < CH; c++) cnt[t * 33 + ns[t * CH + c]]++;
    }
    __syncthreads();
    if (t < 33) {
        int run = 0;
        for (int u = 0; u < 128; u++) { int v = cnt[u * 33 + t]; cnt[u * 33 + t] = run; run += v; }
        base[t] = run;
    }
    __syncthreads();
    if (t == 0) {
        int acc = 0;
        for (int n = 0; n < 33; n++) { int v = base[n]; base[n] = acc; acc += v; }
        base[33] = acc;
    }
    __syncthreads();
    if (t < 128) {
        uint32_t* ord = g_ord2 + (size_t)b * D1;
        uint32_t* inv = g_inv2 + (size_t)b * D1;
        for (int c = 0; c < CH; c++) {
            int i = t * CH + c;
            int n = ns[i];
            int pos = base[n] + cnt[t * 33 + n];
            cnt[t * 33 + n]++;
            ord[pos] = (uint32_t)i;
            inv[i] = (uint32_t)pos;
        }
    }
    if (t < 34) g_seg2[b * 34 + t] = base[t];
}

// ---------------- output gather ----------------
__global__ void out_kernel(const int* __restrict__ idx_out, float* __restrict__ out) {
    int b = blockIdx.x, j = threadIdx.x;
    if (j < D2OUT) out[b * D2OUT + j] = (float)g_cnt2[b * D2OUT + idx_out[j]];
}

// ---------------- launch ----------------
extern "C" void kernel_launch(void* const* d_in, const int* in_sizes, int n_in,
                              void* d_out, int out_size) {
    (void)in_sizes; (void)n_in; (void)out_size;
    const float* x       = (const float*)d_in[0];
    const float* w0      = (const float*)d_in[1];
    const float* t0      = (const float*)d_in[2];
    const float* w2      = (const float*)d_in[3];
    const float* t2      = (const float*)d_in[4];
    const int*   idx0    = (const int*)d_in[5];
    const int*   idx1    = (const int*)d_in[6];
    const int*   idx2    = (const int*)d_in[7];
    const int*   idx_out = (const int*)d_in[8];
    float* out = (float*)d_out;

    const int SMEM_TOTAL = 2 * 49152;   // 96 KB -> 2 CTAs/SM (proven best regime)
    cudaFuncSetAttribute(gemm_lif_kernel<0>, cudaFuncAttributeMaxDynamicSharedMemorySize, SMEM_TOTAL);
    cudaFuncSetAttribute(gemm_lif_kernel<1>, cudaFuncAttributeMaxDynamicSharedMemorySize, SMEM_TOTAL);

    split0_kernel<<<(int)(((size_t)D0 * D0) / 256), 256>>>(w0);
    split2_kernel<<<(D2OUT * D1) / 256, 256>>>(w2);

    buildA0_kernel<<<dim3(D0 / 1024, BB), 256>>>(x, idx0);
    sort0_kernel<<<BB, 128>>>(x, idx0);
    gemm_lif_kernel<0><<<dim3(D0 / 128, MROWS / 128), 256, SMEM_TOTAL>>>(t0);
    fixup_kernel<0><<<2048, 32, D0 * 4>>>(w0, t0);

    mid_kernel<<<BB, 1024>>>(idx1, idx2);
    gemm_lif_kernel<1><<<dim3(D1 / 128, MROWS / 128), 256, SMEM_TOTAL>>>(t2);
    fixup_kernel<1><<<512, 32, D1 * 4>>>(w2, t2);

    out_kernel<<<BB, 1024>>>(idx_out, out);
}

// round 17
// speedup vs baseline: 1.7955x; 1.0068x over previous
#include <cuda_runtime.h>
#include <cuda_bf16.h>
#include <cstdint>
#include <math.h>

// ---------------- problem constants ----------------
#define BB     64
#define D0     4096
#define D1     1024
#define D2OUT  1000
#define TT     32
#define MROWS  (BB * TT)          // 2048 GEMM rows
#define DELTA  1e-3f              // borderline-gap threshold for exact fix-up

// ---------------- device scratch (static globals; no runtime alloc) ----------------
__device__ __nv_bfloat16 g_Bh[(size_t)D0 * D0];    // w0 hi split
__device__ __nv_bfloat16 g_Bm[(size_t)D0 * D0];    // w0 mid split
__device__ __nv_bfloat16 g_B2h[(size_t)D1 * D1];   // w2 splits; rows >= 1000 stay zero
__device__ __nv_bfloat16 g_B2m[(size_t)D1 * D1];
__device__ __nv_bfloat16 g_A[(size_t)MROWS * D0];  // spike matrix (ld 4096 L0 / 1024 L2)
__device__ int           g_cnt0[BB * D0];
__device__ unsigned char g_N1[BB * D1];
__device__ int           g_cnt2[BB * D2OUT];
__device__ uint32_t      g_ord0[BB * D0];
__device__ uint32_t      g_inv0[BB * D0];          // inverse permutation: inv[i] = sorted pos
__device__ int           g_seg0[BB * 34];
__device__ uint32_t      g_ord2[BB * D1];
__device__ uint32_t      g_inv2[BB * D1];
__device__ int           g_seg2[BB * 34];
__device__ int           g_nwork0;                 // worklist sizes (zeroed in buildA0)
__device__ int           g_nwork2;
__device__ uint32_t      g_work0[BB * D0];         // packed flagged indices b*JMAX+j
__device__ uint32_t      g_work2[BB * D2OUT];

// ---------------- PTX helpers (base sm_103-legal only) ----------------
__device__ __forceinline__ uint32_t smem_u32(const void* p) {
    uint32_t a;
    asm("{ .reg .u64 t; cvta.to.shared.u64 t, %1; cvt.u32.u64 %0, t; }" : "=r"(a) : "l"(p));
    return a;
}
#define CP_ASYNC16(dst, src) \
    asm volatile("cp.async.cg.shared.global [%0], [%1], 16;" :: "r"(dst), "l"(src) : "memory")
#define CP_COMMIT() asm volatile("cp.async.commit_group;" ::: "memory")
#define CP_WAIT1()  asm volatile("cp.async.wait_group 1;" ::: "memory")
#define CP_WAIT0()  asm volatile("cp.async.wait_group 0;" ::: "memory")
#define LDSM4(r0, r1, r2, r3, addr)                                              \
    asm volatile("ldmatrix.sync.aligned.m8n8.x4.shared.b16 {%0,%1,%2,%3}, [%4];" \
                 : "=r"(r0), "=r"(r1), "=r"(r2), "=r"(r3) : "r"(addr))
#define MMA16816(d, a, b0, b1)                                                      \
    asm volatile("mma.sync.aligned.m16n8k16.row.col.f32.bf16.bf16.f32 "             \
                 "{%0,%1,%2,%3},{%4,%5,%6,%7},{%8,%9},{%0,%1,%2,%3};"               \
                 : "+f"((d)[0]), "+f"((d)[1]), "+f"((d)[2]), "+f"((d)[3])           \
                 : "r"((a)[0]), "r"((a)[1]), "r"((a)[2]), "r"((a)[3]),              \
                   "r"(b0), "r"(b1))
#define SWZ128(off) ((off) ^ (((off) >> 3) & 0x70))

// ---------------- uniform spike pattern (reference fp32 semantics) ----------------
__device__ __forceinline__ uint32_t pattern_mask(int n) {
    if (n <= 0)  return 0u;
    if (n >= TT) return 0xFFFFFFFFu;
    float spacing = __fdiv_rn(32.0f, (float)n);
    uint32_t m = 0u;
    for (int c = 0; c < TT; c++) {
        double r = fmod((double)c, (double)spacing);
        if (r < 1.0) m |= (1u << c);
    }
    return m;
}

// ---------------- weight splits: w = hi + mid (+ tiny residual handled by fix-up) ------
__global__ void split0_kernel(const float* __restrict__ w) {
    size_t idx = (size_t)blockIdx.x * 256 + threadIdx.x;
    float wv = w[idx];
    __nv_bfloat16 h = __float2bfloat16(wv);
    g_Bh[idx] = h; g_Bm[idx] = __float2bfloat16(wv - __bfloat162float(h));
}
__global__ void split2_kernel(const float* __restrict__ w) {
    size_t idx = (size_t)blockIdx.x * 256 + threadIdx.x;   // covers 1000*1024 exactly
    float wv = w[idx];
    __nv_bfloat16 h = __float2bfloat16(wv);
    g_B2h[idx] = h; g_B2m[idx] = __float2bfloat16(wv - __bfloat162float(h));
}

// ---------------- spike-matrix build, layer 0 (4 i's per thread, 64-bit stores) --------
// Also zeroes the worklist counters (runs before both GEMMs in stream order).
__global__ void buildA0_kernel(const float* __restrict__ x, const int* __restrict__ idx0) {
    __shared__ uint32_t spat[33];
    int tid = threadIdx.x;
    if (tid < 33) spat[tid] = pattern_mask(tid);
    if (blockIdx.x == 0 && blockIdx.y == 0 && tid == 0) { g_nwork0 = 0; g_nwork2 = 0; }
    __syncthreads();
    int b = blockIdx.y;
    int i0 = blockIdx.x * 1024 + tid * 4;
    uint32_t m0 = spat[__float2int_rn(x[b * D0 + idx0[i0 + 0]] * 32.0f)];
    uint32_t m1 = spat[__float2int_rn(x[b * D0 + idx0[i0 + 1]] * 32.0f)];
    uint32_t m2 = spat[__float2int_rn(x[b * D0 + idx0[i0 + 2]] * 32.0f)];
    uint32_t m3 = spat[__float2int_rn(x[b * D0 + idx0[i0 + 3]] * 32.0f)];
#pragma unroll
    for (int t = 0; t < TT; t++) {
        uint64_t v = (uint64_t)(((m0 >> t) & 1u) * 0x3F80u)
                   | ((uint64_t)(((m1 >> t) & 1u) * 0x3F80u) << 16)
                   | ((uint64_t)(((m2 >> t) & 1u) * 0x3F80u) << 32)
                   | ((uint64_t)(((m3 >> t) & 1u) * 0x3F80u) << 48);
        *(uint64_t*)((unsigned short*)g_A + (size_t)(b * TT + t) * D0 + i0) = v;
    }
}

// ---------------- deterministic bucket sort, layer 0 (identical ord/seg/inv) -----------
__global__ void sort0_kernel(const float* __restrict__ x, const int* __restrict__ idxg) {
    __shared__ unsigned char ns[D0];
    __shared__ int cnt[128 * 33];
    __shared__ int base[34];
    int b = blockIdx.x, t = threadIdx.x;
    constexpr int CH = D0 / 128;

    for (int i = t; i < D0; i += 128)
        ns[i] = (unsigned char)__float2int_rn(x[b * D0 + idxg[i]] * 32.0f);
#pragma unroll
    for (int n = 0; n < 33; n++) cnt[t * 33 + n] = 0;
    __syncthreads();
    for (int c = 0; c < CH; c++) cnt[t * 33 + ns[t * CH + c]]++;
    __syncthreads();
    if (t < 33) {
        int run = 0;
        for (int u = 0; u < 128; u++) { int v = cnt[u * 33 + t]; cnt[u * 33 + t] = run; run += v; }
        base[t] = run;
    }
    __syncthreads();
    if (t == 0) {
        int acc = 0;
        for (int n = 0; n < 33; n++) { int v = base[n]; base[n] = acc; acc += v; }
        base[33] = acc;
    }
    __syncthreads();
    uint32_t* ord = g_ord0 + (size_t)b * D0;
    uint32_t* inv = g_inv0 + (size_t)b * D0;
    for (int c = 0; c < CH; c++) {
        int i = t * CH + c;
        int n = ns[i];
        int pos = base[n] + cnt[t * 33 + n];
        cnt[t * 33 + n]++;
        ord[pos] = (uint32_t)i;
        inv[i] = (uint32_t)pos;
    }
    if (t < 34) g_seg0[b * 34 + t] = base[t];
}

// ---------------- GEMM (2 bf16 splits) + fused LIF scan + direct worklist append -------
// Block tile 128x128, warp tile 64x32 (warp grid 2m x 4n): B fragments amortized over
// 4 m-frags -> 8 LDSM4 per ks (vs 10), same 32 MMAs, same 64 acc regs. 2 CTAs/SM.
template <int L>
__global__ void __launch_bounds__(256, 2) gemm_lif_kernel(const float* __restrict__ thr_p) {
    constexpr int KTOT = (L == 0) ? D0 : D1;
    constexpr int NC   = KTOT / 64;
    constexpr int JMAX = (L == 0) ? D0 : D2OUT;
    constexpr uint32_t STAGE = 49152u;   // A(16K) + Bh(16K) + Bm(16K)

    extern __shared__ char smem[];
    uint32_t sb = smem_u32(smem);
    int tid = threadIdx.x, wid = tid >> 5, lane = tid & 31;
    int n0 = blockIdx.x * 128, m0 = blockIdx.y * 128;
    int wm = wid >> 2, wn = wid & 3;          // warp grid 2(m) x 4(n)
    const int mW = wm * 64, nW = wn * 32;

    const __nv_bfloat16* Bs[2];
    if (L == 0) { Bs[0] = g_Bh; Bs[1] = g_Bm; }
    else        { Bs[0] = g_B2h; Bs[1] = g_B2m; }

    auto load_stage = [&](int stage, int kc) {
        uint32_t st = sb + (uint32_t)stage * STAGE;
        int k0 = kc * 64;
#pragma unroll
        for (int u = 0; u < 4; u++) {
            int slot = u * 256 + tid, r = slot >> 3, kk = slot & 7;
            const __nv_bfloat16* gp = g_A + (size_t)(m0 + r) * KTOT + k0 + kk * 8;
            CP_ASYNC16(st + SWZ128((uint32_t)(r * 128 + kk * 16)), gp);
        }
#pragma unroll
        for (int s = 0; s < 2; s++) {
            uint32_t bb = st + 16384u * (1 + s);
#pragma unroll
            for (int u = 0; u < 4; u++) {
                int slot = u * 256 + tid, r = slot >> 3, kk = slot & 7;
                const __nv_bfloat16* gp = Bs[s] + (size_t)(n0 + r) * KTOT + k0 + kk * 8;
                CP_ASYNC16(bb + SWZ128((uint32_t)(r * 128 + kk * 16)), gp);
            }
        }
        CP_COMMIT();
    };

    float acc[4][4][4];
#pragma unroll
    for (int a = 0; a < 4; a++)
#pragma unroll
        for (int b = 0; b < 4; b++)
#pragma unroll
            for (int c = 0; c < 4; c++) acc[a][b][c] = 0.f;

    int q = lane >> 3, w8 = lane & 7;

    load_stage(0, 0);
#pragma unroll 1
    for (int c = 0; c < NC; c++) {
        if (c + 1 < NC) { load_stage((c + 1) & 1, c + 1); CP_WAIT1(); }
        else            { CP_WAIT0(); }
        __syncthreads();

        uint32_t st = sb + (uint32_t)(c & 1) * STAGE;
#pragma unroll
        for (int ks = 0; ks < 4; ks++) {
            uint32_t af[4][4];
#pragma unroll
            for (int mf = 0; mf < 4; mf++) {
                int row = mW + mf * 16 + w8 + (q & 1) * 8;
                int colb = ks * 32 + (q >> 1) * 16;
                LDSM4(af[mf][0], af[mf][1], af[mf][2], af[mf][3],
                      st + SWZ128((uint32_t)(row * 128 + colb)));
            }
#pragma unroll
            for (int s = 0; s < 2; s++) {
                uint32_t bbase = st + 16384u * (1 + s);
#pragma unroll
                for (int h = 0; h < 2; h++) {
                    uint32_t b0, b1, b2, b3;
                    int row = nW + h * 16 + w8 + (q >> 1) * 8;
                    int colb = ks * 32 + (q & 1) * 16;
                    LDSM4(b0, b1, b2, b3, bbase + SWZ128((uint32_t)(row * 128 + colb)));
#pragma unroll
                    for (int mf = 0; mf < 4; mf++) {
                        MMA16816(acc[mf][2 * h + 0], af[mf], b0, b1);
                        MMA16816(acc[mf][2 * h + 1], af[mf], b2, b3);
                    }
                }
            }
        }
        __syncthreads();
    }

    // ---- epilogue: transpose C through padded smem tile, LIF scan + worklist append ----
    float* ct = (float*)smem;                         // [128][129] fp32 (66 KB < 96 KB)
#pragma unroll
    for (int mf = 0; mf < 4; mf++)
#pragma unroll
        for (int nf = 0; nf < 4; nf++) {
            int row = mW + mf * 16 + (lane >> 2);
            int col = nW + nf * 8 + 2 * (lane & 3);
            ct[row * 129 + col]           = acc[mf][nf][0];
            ct[row * 129 + col + 1]       = acc[mf][nf][1];
            ct[(row + 8) * 129 + col]     = acc[mf][nf][2];
            ct[(row + 8) * 129 + col + 1] = acc[mf][nf][3];
        }
    __syncthreads();

    float thr = *thr_p;
    int* cnt_out = (L == 0) ? g_cnt0 : g_cnt2;
#pragma unroll
    for (int pp = 0; pp < 2; pp++) {
        int p = pp * 256 + tid;
        int bl = p >> 7, j = p & 127;
        float memb = 0.f, ming = 1e30f;
        int cnt = 0;
#pragma unroll
        for (int t = 0; t < TT; t++) {
            memb += ct[(bl * 32 + t) * 129 + j];
            float g = fabsf(memb - thr);
            if (g < ming) ming = g;
            if (memb > thr) { memb -= thr; cnt++; }
        }
        int bglob = blockIdx.y * 4 + bl;
        int jglob = n0 + j;
        if (jglob < JMAX) {
            cnt_out[(size_t)bglob * JMAX + jglob] = cnt;
            if (ming < DELTA) {   // direct worklist append (order-independent results)
                int pos = atomicAdd((L == 0) ? &g_nwork0 : &g_nwork2, 1);
                ((L == 0) ? g_work0 : g_work2)[pos] = (uint32_t)(bglob * JMAX + jglob);
            }
        }
    }
}

// ---------------- exact fix-up: warp-per-row, coalesced gather to smem, serial consume ----
// Byte-identical value/add order to the thrice-verified R1 path.
template <int L>
__global__ void __launch_bounds__(32) fixup_kernel(const float* __restrict__ w,
                                                   const float* __restrict__ thr_p) {
    constexpr int K    = (L == 0) ? D0 : D1;
    constexpr int JMAX = (L == 0) ? D0 : D2OUT;
    extern __shared__ float sw[];                 // K floats
    __shared__ uint32_t spat[33];
    int lane = threadIdx.x;
    for (int n = lane; n < 33; n += 32) spat[n] = pattern_mask(n);
    __syncwarp();

    int nwork = (L == 0) ? g_nwork0 : g_nwork2;
    const uint32_t* work = (L == 0) ? g_work0 : g_work2;
    float thr = *thr_p;

    for (int wi = blockIdx.x; wi < nwork; wi += gridDim.x) {
        int idx = (int)work[wi];
        int b = idx / JMAX, j = idx % JMAX;
        const uint32_t* inv = ((L == 0) ? g_inv0 : g_inv2) + (size_t)b * K;
        const float* wrow = w + (size_t)j * K;

#pragma unroll 4
        for (int i = lane; i < K; i += 32) sw[inv[i]] = wrow[i];
        __syncwarp();

        if (lane == 0) {
            const int* sg = ((L == 0) ? g_seg0 : g_seg2) + b * 34;
            float I[TT];
#pragma unroll
            for (int t = 0; t < TT; t++) I[t] = 0.f;

#pragma unroll 1
            for (int n = 1; n < 33; n++) {
                int s = sg[n], e = sg[n + 1];
                if (s >= e) continue;
                float a0 = 0.f, a1 = 0.f, a2 = 0.f, a3 = 0.f;
                int k = s;
                float p0 = 0.f, p1 = 0.f, p2 = 0.f, p3 = 0.f;
                if (k + 4 <= e) { p0 = sw[k]; p1 = sw[k + 1]; p2 = sw[k + 2]; p3 = sw[k + 3]; }
#pragma unroll 1
                for (; k + 4 <= e; ) {
                    float c0 = p0, c1 = p1, c2 = p2, c3 = p3;
                    int kn = k + 4;
                    if (kn + 4 <= e) { p0 = sw[kn]; p1 = sw[kn + 1]; p2 = sw[kn + 2]; p3 = sw[kn + 3]; }
                    a0 += c0; a1 += c1; a2 += c2; a3 += c3;   // R1 add order
                    k = kn;
                }
                for (; k < e; k++) a0 += sw[k];
                float acc = (a0 + a1) + (a2 + a3);
                uint32_t m = spat[n];
#pragma unroll
                for (int t = 0; t < TT; t++)
                    if ((m >> t) & 1u) I[t] += acc;
            }

            float memb = 0.f;
            int cnt = 0;
#pragma unroll
            for (int t = 0; t < TT; t++) {
                memb += I[t];
                if (memb > thr) { memb -= thr; cnt++; }
            }
            if (L == 0) g_cnt0[b * D0 + j] = cnt; else g_cnt2[b * D2OUT + j] = cnt;
        }
        __syncwarp();
    }
}

// ---------------- fused middle stage: pooling + re-encode + buildA2 + sort2 ------------
__global__ void mid_kernel(const int* __restrict__ idx1, const int* __restrict__ idx2) {
    __shared__ uint32_t spat[33];
    __shared__ unsigned char ns[D1];
    __shared__ int cnt[128 * 33];
    __shared__ int base[34];
    int b = blockIdx.x, t = threadIdx.x;

    if (t < 33) spat[t] = pattern_mask(t);

    // phase 1: avg-pool spike counts -> N1 (exact integer/pow2 arithmetic)
    {
        int p = t;   // 0..1023
        int ch = p >> 4, oh = (p >> 2) & 3, ow = p & 3;
        int c = 0;
#pragma unroll
        for (int dh = 0; dh < 2; dh++)
#pragma unroll
            for (int dw = 0; dw < 2; dw++) {
                int k = ch * 64 + (2 * oh + dh) * 8 + (2 * ow + dw);
                c += g_cnt0[b * D0 + idx1[k]];
            }
        g_N1[b * D1 + p] = (unsigned char)__float2int_rn((float)c * 0.25f);
    }
    __syncthreads();

    // phase 2: gather bucket ids through idx2 + build A2 (4 i's per thread, u64 stores)
    if (t < 256) {
        int i0 = t * 4;
        uint32_t m0 = spat[g_N1[b * D1 + idx2[i0 + 0]]];
        uint32_t m1 = spat[g_N1[b * D1 + idx2[i0 + 1]]];
        uint32_t m2 = spat[g_N1[b * D1 + idx2[i0 + 2]]];
        uint32_t m3 = spat[g_N1[b * D1 + idx2[i0 + 3]]];
#pragma unroll
        for (int tt = 0; tt < TT; tt++) {
            uint64_t v = (uint64_t)(((m0 >> tt) & 1u) * 0x3F80u)
                       | ((uint64_t)(((m1 >> tt) & 1u) * 0x3F80u) << 16)
                       | ((uint64_t)(((m2 >> tt) & 1u) * 0x3F80u) << 32)
                       | ((uint64_t)(((m3 >> tt) & 1u) * 0x3F80u) << 48);
            *(uint64_t*)((unsigned short*)g_A + (size_t)(b * TT + tt) * D1 + i0) = v;
        }
    }
    ns[t] = g_N1[b * D1 + idx2[t]];
    __syncthreads();

    // phase 3: counting sort (threads < 128), CH = 8
    constexpr int CH = D1 / 128;
    if (t < 128) {
#pragma unroll
        for (int n = 0; n < 33; n++) cnt[t * 33 + n] = 0;
        for (int c = 0; c < CH; c++) cnt[t * 33 + ns[t * CH + c]]++;
    }
    __syncthreads();
    if (t < 33) {
        int run = 0;
        for (int u = 0; u < 128; u++) { int v = cnt[u * 33 + t]; cnt[u * 33 + t] = run; run += v; }
        base[t] = run;
    }
    __syncthreads();
    if (t == 0) {
        int acc = 0;
        for (int n = 0; n < 33; n++) { int v = base[n]; base[n] = acc; acc += v; }
        base[33] = acc;
    }
    __syncthreads();
    if (t < 128) {
        uint32_t* ord = g_ord2 + (size_t)b * D1;
        uint32_t* inv = g_inv2 + (size_t)b * D1;
        for (int c = 0; c < CH; c++) {
            int i = t * CH + c;
            int n = ns[i];
            int pos = base[n] + cnt[t * 33 + n];
            cnt[t * 33 + n]++;
            ord[pos] = (uint32_t)i;
            inv[i] = (uint32_t)pos;
        }
    }
    if (t < 34) g_seg2[b * 34 + t] = base[t];
}

// ---------------- output gather ----------------
__global__ void out_kernel(const int* __restrict__ idx_out, float* __restrict__ out) {
    int b = blockIdx.x, j = threadIdx.x;
    if (j < D2OUT) out[b * D2OUT + j] = (float)g_cnt2[b * D2OUT + idx_out[j]];
}

// ---------------- launch (ordered so gemm0 is launch #4 -> ncu captures it) ------------
extern "C" void kernel_launch(void* const* d_in, const int* in_sizes, int n_in,
                              void* d_out, int out_size) {
    (void)in_sizes; (void)n_in; (void)out_size;
    const float* x       = (const float*)d_in[0];
    const float* w0      = (const float*)d_in[1];
    const float* t0      = (const float*)d_in[2];
    const float* w2      = (const float*)d_in[3];
    const float* t2      = (const float*)d_in[4];
    const int*   idx0    = (const int*)d_in[5];
    const int*   idx1    = (const int*)d_in[6];
    const int*   idx2    = (const int*)d_in[7];
    const int*   idx_out = (const int*)d_in[8];
    float* out = (float*)d_out;

    const int SMEM_TOTAL = 2 * 49152;   // 96 KB -> 2 CTAs/SM
    cudaFuncSetAttribute(gemm_lif_kernel<0>, cudaFuncAttributeMaxDynamicSharedMemorySize, SMEM_TOTAL);
    cudaFuncSetAttribute(gemm_lif_kernel<1>, cudaFuncAttributeMaxDynamicSharedMemorySize, SMEM_TOTAL);

    buildA0_kernel<<<dim3(D0 / 1024, BB), 256>>>(x, idx0);            // #1 (zeroes counters)
    sort0_kernel<<<BB, 128>>>(x, idx0);                               // #2
    split0_kernel<<<(int)(((size_t)D0 * D0) / 256), 256>>>(w0);       // #3
    gemm_lif_kernel<0><<<dim3(D0 / 128, MROWS / 128), 256, SMEM_TOTAL>>>(t0);  // #4 <- profiled
    fixup_kernel<0><<<2048, 32, D0 * 4>>>(w0, t0);                    // #5
    split2_kernel<<<(D2OUT * D1) / 256, 256>>>(w2);                   // #6
    mid_kernel<<<BB, 1024>>>(idx1, idx2);                             // #7
    gemm_lif_kernel<1><<<dim3(D1 / 128, MROWS / 128), 256, SMEM_TOTAL>>>(t2);  // #8
    fixup_kernel<1><<<512, 32, D1 * 4>>>(w2, t2);                     // #9
    out_kernel<<<BB, 1024>>>(idx_out, out);                           // #10
}